// round 6
// baseline (speedup 1.0000x reference)
#include <cuda_runtime.h>
#include <cuda_bf16.h>
#include <float.h>

// Problem constants
#define BB   256      // batch
#define TOK  256      // tokens per image
#define NQ   (BB*TOK) // 65536 queries
#define V    1024     // codebook size
#define D    256      // code dim

// Device scratch (allocation-free rule: __device__ globals).
__device__ __align__(16) float g_A[V * V];   // A[r][v] = ||w_v||^2 - 2 w_r . w_v  (4 MB)
__device__ __align__(16) float g_d[V];       // ||w_v||^2
__device__ __align__(16) float g_Wt[D * V];  // W transposed: Wt[d][v]             (1 MB)
__device__ __align__(16) int   g_idx[NQ];    // argmin per query
__device__ __align__(16) int   g_i[NQ];      // decoded seq1 indices
__device__ __align__(16) int   g_j[NQ];      // decoded seq2 indices
__device__ int g_is64;                       // 1 if inputs are int64-layout

// ---------------------------------------------------------------------------
// k_detect: sniff index dtype. int64 layout <=> (viewing as int32 words)
// all odd words are 0 AND even words < V, over the first 256 words.
// For int32 layout the odd words are real random indices (mostly nonzero),
// so this misclassifies with prob ~(1/1024)^128 ~ 0. Deterministic.
// ---------------------------------------------------------------------------
__global__ void k_detect(const int* __restrict__ s1) {
    __shared__ int bad;
    if (threadIdx.x == 0) bad = 0;
    __syncthreads();
    int t = threadIdx.x;             // 0..255
    int w = s1[t];
    if (t & 1) { if (w != 0) atomicOr(&bad, 1); }
    else       { if ((unsigned)w >= V) atomicOr(&bad, 1); }
    __syncthreads();
    if (threadIdx.x == 0) g_is64 = bad ? 0 : 1;
}

// ---------------------------------------------------------------------------
// k_convert: decode indices for both possible layouts, clamp defensively.
// ---------------------------------------------------------------------------
__global__ void k_convert(const int* __restrict__ s1, const int* __restrict__ s2) {
    int n = blockIdx.x * blockDim.x + threadIdx.x;   // covers NQ
    int sh = g_is64;                                 // 0 (int32) or 1 (int64 low word)
    int a = s1[n << sh];
    int b = s2[n << sh];
    g_i[n] = min(max(a, 0), V - 1);
    g_j[n] = min(max(b, 0), V - 1);
}

// ---------------------------------------------------------------------------
// k_rownorm: ||w_v||^2 per row. One warp per row. Scalar loads of W.
// ---------------------------------------------------------------------------
__global__ void k_rownorm(const float* __restrict__ W) {
    int warp = (blockIdx.x * blockDim.x + threadIdx.x) >> 5;
    int lane = threadIdx.x & 31;
    if (warp >= V) return;
    const float* row = W + warp * D;
    float s = 0.0f;
    #pragma unroll
    for (int k = 0; k < D / 32; k++) {
        float w = row[k * 32 + lane];
        s = fmaf(w, w, s);
    }
    #pragma unroll
    for (int off = 16; off > 0; off >>= 1)
        s += __shfl_xor_sync(0xffffffffu, s, off);
    if (lane == 0) g_d[warp] = s;
}

// ---------------------------------------------------------------------------
// k_transposeW: W [V,D] -> Wt [D,V].
// ---------------------------------------------------------------------------
__global__ void k_transposeW(const float* __restrict__ W) {
    int tid = blockIdx.x * blockDim.x + threadIdx.x;   // covers D*V
    int d = tid >> 10;          // / V
    int v = tid & (V - 1);      // % V
    g_Wt[tid] = W[v * D + d];
}

// ---------------------------------------------------------------------------
// k_gemmA: A[r][v] = g_d[v] - 2 * dot(W[r], W[v]).
// 64x64 tile per CTA, 256 threads, 4x4 register tile, BK=16.
// ---------------------------------------------------------------------------
__global__ __launch_bounds__(256) void k_gemmA(const float* __restrict__ W) {
    __shared__ __align__(16) float As[16][64];   // [k][r]
    __shared__ __align__(16) float Bs[16][64];   // [k][v]

    int tid = threadIdx.x;
    int tx = tid & 15;             // v direction
    int ty = tid >> 4;             // r direction
    int r0 = blockIdx.y * 64;
    int v0 = blockIdx.x * 64;

    float acc[4][4];
    #pragma unroll
    for (int i = 0; i < 4; i++)
        #pragma unroll
        for (int j = 0; j < 4; j++) acc[i][j] = 0.f;

    int lrow = tid >> 2;           // 0..63
    int lk4  = (tid & 3) * 4;      // 0,4,8,12

    for (int kt = 0; kt < D; kt += 16) {
        #pragma unroll
        for (int u = 0; u < 4; u++) {
            As[lk4 + u][lrow] = W[(r0 + lrow) * D + kt + lk4 + u];
            Bs[lk4 + u][lrow] = W[(v0 + lrow) * D + kt + lk4 + u];
        }
        __syncthreads();
        #pragma unroll
        for (int kk = 0; kk < 16; kk++) {
            float ar[4], br[4];
            #pragma unroll
            for (int i = 0; i < 4; i++) ar[i] = As[kk][ty * 4 + i];
            #pragma unroll
            for (int j = 0; j < 4; j++) br[j] = Bs[kk][tx * 4 + j];
            #pragma unroll
            for (int i = 0; i < 4; i++)
                #pragma unroll
                for (int j = 0; j < 4; j++)
                    acc[i][j] = fmaf(ar[i], br[j], acc[i][j]);
        }
        __syncthreads();
    }

    #pragma unroll
    for (int j = 0; j < 4; j++) {
        int v = v0 + tx * 4 + j;
        float dv = g_d[v];
        #pragma unroll
        for (int i = 0; i < 4; i++) {
            int r = r0 + ty * 4 + i;
            g_A[r * V + v] = dv - 2.0f * acc[i][j];
        }
    }
}

// ---------------------------------------------------------------------------
// k_argmin: one warp per query. score(v) = c1*A[i][v] + c2*A[j][v].
// float4 loads on g_A (16B-aligned __device__ global, offsets 16B-multiple).
// Lane l scans v = k*128 + l*4 + c ascending; strict < keeps the first
// minimum; cross-lane tie-break takes the lower index => matches argmin.
// ---------------------------------------------------------------------------
__global__ __launch_bounds__(256) void k_argmin(const float* __restrict__ alpha) {
    int warp = threadIdx.x >> 5;
    int lane = threadIdx.x & 31;
    int n = blockIdx.x * 8 + warp;

    float a  = alpha[0];
    float c1 = 1.0f - a;
    float c2 = a;
    int i = g_i[n];
    int j = g_j[n];

    const float4* Ai = (const float4*)(g_A + i * V);
    const float4* Aj = (const float4*)(g_A + j * V);

    float best = FLT_MAX;
    int bidx = 0;

    #pragma unroll
    for (int k = 0; k < 8; k++) {
        int vb = k * 128 + lane * 4;
        float4 x = Ai[k * 32 + lane];
        float4 y = Aj[k * 32 + lane];
        float s;
        s = fmaf(c2, y.x, c1 * x.x); if (s < best) { best = s; bidx = vb;     }
        s = fmaf(c2, y.y, c1 * x.y); if (s < best) { best = s; bidx = vb + 1; }
        s = fmaf(c2, y.z, c1 * x.z); if (s < best) { best = s; bidx = vb + 2; }
        s = fmaf(c2, y.w, c1 * x.w); if (s < best) { best = s; bidx = vb + 3; }
    }

    #pragma unroll
    for (int off = 16; off > 0; off >>= 1) {
        float ob = __shfl_xor_sync(0xffffffffu, best, off);
        int   oi = __shfl_xor_sync(0xffffffffu, bidx, off);
        if (ob < best || (ob == best && oi < bidx)) { best = ob; bidx = oi; }
    }
    if (lane == 0) g_idx[n] = bidx;
}

// ---------------------------------------------------------------------------
// k_gather: out[b][d][t] = Wt[d][ idx[b][t] ],  t = h*16+w (0..255).
// CTA handles 8 b's x 8 d's; Wt rows + idx rows staged in smem.
// Fully-coalesced 1KB store runs to d_out.
// ---------------------------------------------------------------------------
__global__ __launch_bounds__(256) void k_gather(float* __restrict__ out) {
    __shared__ __align__(16) float wt_s[8][V];     // 32 KB
    __shared__ __align__(16) int   idx_s[8][TOK];  // 8 KB

    int t  = threadIdx.x;            // 0..255
    int b0 = blockIdx.x * 8;
    int d0 = blockIdx.y * 8;

    #pragma unroll
    for (int q = 0; q < 32; q++) {
        int lin = q * 256 + t;
        int r = lin >> 10, c = lin & (V - 1);
        wt_s[r][c] = g_Wt[(d0 + r) * V + c];
    }
    #pragma unroll
    for (int q = 0; q < 8; q++) {
        int lin = q * 256 + t;
        int bl = lin >> 8, tt = lin & 255;
        idx_s[bl][tt] = g_idx[(b0 + bl) * TOK + tt];
    }
    __syncthreads();

    #pragma unroll
    for (int bl = 0; bl < 8; bl++) {
        int myidx = idx_s[bl][t];
        #pragma unroll
        for (int dl = 0; dl < 8; dl++) {
            out[(((long)(b0 + bl) * D) + (d0 + dl)) * TOK + t] = wt_s[dl][myidx];
        }
    }
}

// ---------------------------------------------------------------------------
extern "C" void kernel_launch(void* const* d_in, const int* in_sizes, int n_in,
                              void* d_out, int out_size) {
    const int*   seq1  = (const int*)d_in[0];    // int32 words (int64 handled via g_is64)
    const int*   seq2  = (const int*)d_in[1];
    const float* alpha = (const float*)d_in[2];
    const float* W     = (const float*)d_in[3];
    float* out = (float*)d_out;

    k_detect<<<1, 256>>>(seq1);                       // sniff index dtype
    k_convert<<<NQ / 256, 256>>>(seq1, seq2);         // decode + clamp indices
    k_rownorm<<<128, 256>>>(W);                       // ||w||^2, 1024 warps
    k_transposeW<<<(D * V) / 256, 256>>>(W);          // Wt for gather
    dim3 ggrid(V / 64, V / 64);
    k_gemmA<<<ggrid, 256>>>(W);                       // build A table
    k_argmin<<<NQ / 8, 256>>>(alpha);                 // 8 warps / CTA
    dim3 grid(BB / 8, D / 8);
    k_gather<<<grid, 256>>>(out);                     // gather + BCHW layout
}